// round 12
// baseline (speedup 1.0000x reference)
#include <cuda_runtime.h>
#include <cuda_fp16.h>

#define L_TOTAL 32768
#define KQ      1024
#define EDIM    64
#define MT      32             // latents per CTA (2 tiles x 16)
#define KHALF   512            // codes per k-split half
#define CHK     16             // codes per staged chunk per half
#define NCHUNK  (KHALF / CHK)  // 32
#define SROW    72             // padded smem row stride (halves) -> conflict-free
#define THREADS 128

// scratch tables (no cudaMalloc allowed)
__device__ float  g_c[KQ];             // ||e_k||^2 (fp32)
__device__ __half g_ehi[KQ * EDIM];    // fp16-rounded embeddings [k][e]
__device__ __half g_elo[KQ * EDIM];    // residual

__device__ __forceinline__ void mma16816(float* d, const unsigned* a,
                                         unsigned b0, unsigned b1) {
    asm volatile(
        "mma.sync.aligned.m16n8k16.row.col.f32.f16.f16.f32 "
        "{%0,%1,%2,%3}, {%4,%5,%6,%7}, {%8,%9}, {%0,%1,%2,%3};"
        : "+f"(d[0]), "+f"(d[1]), "+f"(d[2]), "+f"(d[3])
        : "r"(a[0]), "r"(a[1]), "r"(a[2]), "r"(a[3]), "r"(b0), "r"(b1));
}

__device__ __forceinline__ void ldsm4(unsigned& r0, unsigned& r1,
                                      unsigned& r2, unsigned& r3,
                                      unsigned addr) {
    asm volatile("ldmatrix.sync.aligned.m8n8.x4.shared.b16 {%0,%1,%2,%3}, [%4];"
                 : "=r"(r0), "=r"(r1), "=r"(r2), "=r"(r3) : "r"(addr));
}

__device__ __forceinline__ unsigned packsplit(float a, float b, unsigned& lo) {
    __half ha = __float2half_rn(a), hb = __float2half_rn(b);
    float la = a - __half2float(ha), lb = b - __half2float(hb);
    __half2 H = __halves2half2(ha, hb);
    __half2 L = __halves2half2(__float2half_rn(la), __float2half_rn(lb));
    lo = *reinterpret_cast<unsigned*>(&L);
    return *reinterpret_cast<unsigned*>(&H);
}

__device__ __forceinline__ unsigned packhi(float a, float b) {
    __half2 H = __halves2half2(__float2half_rn(a), __float2half_rn(b));
    return *reinterpret_cast<unsigned*>(&H);
}

__device__ __forceinline__ void cp16(void* dst_smem, const void* src) {
    unsigned d = (unsigned)__cvta_generic_to_shared(dst_smem);
    asm volatile("cp.async.cg.shared.global [%0], [%1], 16;"
                 :: "r"(d), "l"(src) : "memory");
}

// Parallel prep: 8 threads per code row. ||e||^2 via 8-lane shfl tree.
__global__ void vq_prep_kernel(const float* __restrict__ emb) {
    int t   = blockIdx.x * blockDim.x + threadIdx.x;  // 0..8191
    int k   = t >> 3;
    int seg = t & 7;
    const float4* p = reinterpret_cast<const float4*>(emb + k * EDIM + seg * 8);
    float4 v0 = p[0], v1 = p[1];
    float s = v0.x * v0.x + v0.y * v0.y + v0.z * v0.z + v0.w * v0.w
            + v1.x * v1.x + v1.y * v1.y + v1.z * v1.z + v1.w * v1.w;
    uint4 H, L;
    H.x = packsplit(v0.x, v0.y, L.x);
    H.y = packsplit(v0.z, v0.w, L.y);
    H.z = packsplit(v1.x, v1.y, L.z);
    H.w = packsplit(v1.z, v1.w, L.w);
    *reinterpret_cast<uint4*>(&g_ehi[k * EDIM + seg * 8]) = H;
    *reinterpret_cast<uint4*>(&g_elo[k * EDIM + seg * 8]) = L;
    s += __shfl_xor_sync(0xffffffffu, s, 1);
    s += __shfl_xor_sync(0xffffffffu, s, 2);
    s += __shfl_xor_sync(0xffffffffu, s, 4);
    if (seg == 0) g_c[k] = s;
}

struct Top2 { float b1, b2; int i1, i2; };

__device__ __forceinline__ void upd(Top2& t, float s, int c) {
    if (s < t.b1)      { t.b2 = t.b1; t.i2 = t.i1; t.b1 = s; t.i1 = c; }
    else if (s < t.b2) { t.b2 = s; t.i2 = c; }
}

__global__ void __launch_bounds__(THREADS, 7)
vq_mma_kernel(const float* __restrict__ x,
              const float* __restrict__ emb,
              float* __restrict__ out) {
    // [buf][half][tab(hi/lo)] double-buffered code chunks
    __shared__ __align__(16) __half sB[2][2][2][CHK * SROW];
    __shared__ float cs[KQ];
    __shared__ float mb1[MT], mb2[MT];
    __shared__ int   mi1[MT], mi2[MT];
    __shared__ int   sidx[MT];

    const int tid   = threadIdx.x;
    const int warp  = tid >> 5;
    const int lane  = tid & 31;
    const int g     = lane >> 2;       // row within m16 tile
    const int T     = lane & 3;        // thread in quad
    const int tile  = warp & 1;        // which 16-latent tile
    const int khalf = warp >> 1;       // which 512-code half (pair id)
    const int ptid  = tid & 63;        // thread id within the k-half pair
    const int lbase = blockIdx.x * MT;

    // stage ||e||^2
    #pragma unroll
    for (int i = 0; i < KQ / THREADS; i++)
        cs[tid + i * THREADS] = g_c[tid + i * THREADS];

    // Pair-scoped staging: the 64 threads of this k-half pair stage THEIR
    // half's chunk (hi+lo): 256 16B moves -> 4 per thread.
    auto stage = [&](int ch, int buf) {
        #pragma unroll
        for (int i = 0; i < 4; i++) {
            int u   = ptid + i * 64;           // 0..255
            int seg = u & 7;
            int row = (u >> 3) & 15;
            int tab = u >> 7;
            const __half* src = tab ? g_elo : g_ehi;
            cp16(&sB[buf][khalf][tab][row * SROW + seg * 8],
                 &src[(size_t)(khalf * KHALF + ch * CHK + row) * EDIM + seg * 8]);
        }
        asm volatile("cp.async.commit_group;" ::: "memory");
    };

    stage(0, 0);

    // ldmatrix per-lane base offsets (verified mapping, rel_err 0.0):
    const unsigned lane_off =
        (unsigned)(((lane & 7) + ((lane >> 4) << 3)) * (SROW * 2)
                   + ((lane >> 3) & 1) * 16);
    const unsigned sm_hi0 =
        (unsigned)__cvta_generic_to_shared(&sB[0][khalf][0][0]) + lane_off;
    const unsigned sm_lo0 =
        (unsigned)__cvta_generic_to_shared(&sB[0][khalf][1][0]) + lane_off;
    const unsigned BUFSTRIDE = 2u * 2u * CHK * SROW * 2u;   // bytes per buf

    // A fragments: rows r0 = tile*16+g, r1 = r0+8 of (-2x), fp16-hi only.
    unsigned ahi[4][4];
    {
        const float* xr0 = x + (size_t)(lbase + tile * 16 + g) * EDIM;
        const float* xr1 = xr0 + 8 * EDIM;
        #pragma unroll
        for (int ks = 0; ks < 4; ks++) {
            int c0 = 16 * ks + 2 * T;
            float2 v;
            v = *reinterpret_cast<const float2*>(xr0 + c0);
            ahi[ks][0] = packhi(-2.f * v.x, -2.f * v.y);
            v = *reinterpret_cast<const float2*>(xr1 + c0);
            ahi[ks][1] = packhi(-2.f * v.x, -2.f * v.y);
            v = *reinterpret_cast<const float2*>(xr0 + c0 + 8);
            ahi[ks][2] = packhi(-2.f * v.x, -2.f * v.y);
            v = *reinterpret_cast<const float2*>(xr1 + c0 + 8);
            ahi[ks][3] = packhi(-2.f * v.x, -2.f * v.y);
        }
    }

    Top2 tp[2];
    tp[0].b1 = tp[0].b2 = 3.4e38f; tp[0].i1 = tp[0].i2 = 0;
    tp[1].b1 = tp[1].b2 = 3.4e38f; tp[1].i1 = tp[1].i2 = 0;

    asm volatile("cp.async.wait_group 0;" ::: "memory");
    __syncthreads();   // covers cs staging + chunk 0 for both pairs

    int buf = 0;
    #pragma unroll 1
    for (int ch = 0; ch < NCHUNK; ch++) {
        if (ch + 1 < NCHUNK) stage(ch + 1, buf ^ 1);   // overlap next stage

        const unsigned base_hi = sm_hi0 + (unsigned)buf * BUFSTRIDE;
        const unsigned base_lo = sm_lo0 + (unsigned)buf * BUFSTRIDE;
        const int c0 = khalf * KHALF + ch * CHK;

        // CHK=16 -> one n16-tile. hi*hi and hi*lo share accumulators
        // (fp32 accumulate; reassociation covered by the 3e-2 guard).
        float d[2][4] = {{0,0,0,0},{0,0,0,0}};
        #pragma unroll
        for (int kh = 0; kh < 2; kh++) {
            unsigned h0[4], h1[4], l0[4], l1[4];
            unsigned ko = (unsigned)(kh * 64);
            ldsm4(h0[0], h0[1], h0[2], h0[3], base_hi + ko);
            ldsm4(h1[0], h1[1], h1[2], h1[3], base_hi + ko + 32);
            ldsm4(l0[0], l0[1], l0[2], l0[3], base_lo + ko);
            ldsm4(l1[0], l1[1], l1[2], l1[3], base_lo + ko + 32);
            int ks = 2 * kh;
            #pragma unroll
            for (int j = 0; j < 2; j++) {
                mma16816(d[j], ahi[ks],     h0[2*j], h0[2*j+1]);  // hi*hi
                mma16816(d[j], ahi[ks],     l0[2*j], l0[2*j+1]);  // hi*lo
                mma16816(d[j], ahi[ks + 1], h1[2*j], h1[2*j+1]);
                mma16816(d[j], ahi[ks + 1], l1[2*j], l1[2*j+1]);
            }
        }
        #pragma unroll
        for (int j = 0; j < 2; j++) {
            int col = c0 + 8 * j + 2 * T;
            upd(tp[0], cs[col]     + d[j][0], col);
            upd(tp[0], cs[col + 1] + d[j][1], col + 1);
            upd(tp[1], cs[col]     + d[j][2], col);
            upd(tp[1], cs[col + 1] + d[j][3], col + 1);
        }

        asm volatile("cp.async.wait_group 0;" ::: "memory");
        // Pair-scoped barrier: only the 2 warps sharing this k-half sync.
        asm volatile("bar.sync %0, %1;" :: "r"(1 + khalf), "r"(64) : "memory");
        buf ^= 1;
    }

    // Reduce across the 4 lanes of each quad (xor 1, 2 stay in-quad).
    #pragma unroll
    for (int s = 0; s < 2; s++) {
        #pragma unroll
        for (int m = 1; m < 4; m <<= 1) {
            float ob1 = __shfl_xor_sync(0xffffffffu, tp[s].b1, m);
            float ob2 = __shfl_xor_sync(0xffffffffu, tp[s].b2, m);
            int   oi1 = __shfl_xor_sync(0xffffffffu, tp[s].i1, m);
            int   oi2 = __shfl_xor_sync(0xffffffffu, tp[s].i2, m);
            bool of = (ob1 < tp[s].b1) || (ob1 == tp[s].b1 && oi1 < tp[s].i1);
            if (of) {
                bool t2 = (tp[s].b1 < ob2) || (tp[s].b1 == ob2 && tp[s].i1 < oi2);
                tp[s].b2 = t2 ? tp[s].b1 : ob2;
                tp[s].i2 = t2 ? tp[s].i1 : oi2;
                tp[s].b1 = ob1; tp[s].i1 = oi1;
            } else {
                bool t2 = (ob1 < tp[s].b2) || (ob1 == tp[s].b2 && oi1 < tp[s].i2);
                if (t2) { tp[s].b2 = ob1; tp[s].i2 = oi1; }
            }
        }
    }

    // k-half merge: khalf1 publishes, khalf0 merges (half0 idx < half1 idx,
    // strict < keeps first-min semantics).
    if (khalf == 1 && T == 0) {
        #pragma unroll
        for (int s = 0; s < 2; s++) {
            int lr = tile * 16 + g + 8 * s;
            mb1[lr] = tp[s].b1; mi1[lr] = tp[s].i1;
            mb2[lr] = tp[s].b2; mi2[lr] = tp[s].i2;
        }
    }
    __syncthreads();

    if (khalf == 0 && T == 0) {
        #pragma unroll
        for (int s = 0; s < 2; s++) {
            int lr = tile * 16 + g + 8 * s;
            float ob1 = mb1[lr], ob2 = mb2[lr];
            int   oi1 = mi1[lr], oi2 = mi2[lr];
            if (ob1 < tp[s].b1) {
                bool t2 = (tp[s].b1 <= ob2);
                tp[s].b2 = t2 ? tp[s].b1 : ob2;
                tp[s].i2 = t2 ? tp[s].i1 : oi2;
                tp[s].b1 = ob1; tp[s].i1 = oi1;
            } else if (ob1 < tp[s].b2) {
                tp[s].b2 = ob1; tp[s].i2 = oi1;
            }

            int win = tp[s].i1;
            // Widened guard (2-pass split): exact fp32 recheck when close.
            if (tp[s].b2 - tp[s].b1 < 3e-2f) {
                const float* xr  = x   + (size_t)(lbase + lr) * EDIM;
                const float* e1r = emb + (size_t)tp[s].i1 * EDIM;
                const float* e2r = emb + (size_t)tp[s].i2 * EDIM;
                float d1 = 0.f, d2 = 0.f;
                #pragma unroll 8
                for (int e = 0; e < EDIM; e++) {
                    float xv = xr[e];
                    d1 = fmaf(xv, e1r[e], d1);
                    d2 = fmaf(xv, e2r[e], d2);
                }
                float s1 = fmaf(-2.f, d1, cs[tp[s].i1]);
                float s2 = fmaf(-2.f, d2, cs[tp[s].i2]);
                if (s2 < s1 || (s2 == s1 && tp[s].i2 < tp[s].i1)) win = tp[s].i2;
            }
            sidx[lr] = win;
        }
    }
    __syncthreads();

    // Coalesced epilogue: out = [x | quantized | z_hat | indices], fp32.
    const size_t LE4 = (size_t)L_TOTAL * (EDIM / 4);
    const float4* x4  = reinterpret_cast<const float4*>(x);
    const float4* e4p = reinterpret_cast<const float4*>(emb);
    float4* out4 = reinterpret_cast<float4*>(out);
    #pragma unroll
    for (int i = 0; i < (MT * EDIM / 4) / THREADS; i++) {
        int idx = tid + i * THREADS;
        int l = idx >> 4, c4 = idx & 15;
        size_t goff = (size_t)(lbase + l) * 16 + c4;
        float4 xv = x4[goff];
        float4 qv = e4p[(size_t)sidx[l] * 16 + c4];
        out4[goff] = xv;
        out4[LE4 + goff] = qv;
        float4 zh;
        zh.x = (xv.x + qv.x) - xv.x;
        zh.y = (xv.y + qv.y) - xv.y;
        zh.z = (xv.z + qv.z) - xv.z;
        zh.w = (xv.w + qv.w) - xv.w;
        out4[2 * LE4 + goff] = zh;
    }
    if (tid < MT)
        out[3 * (size_t)L_TOTAL * EDIM + lbase + tid] = (float)sidx[tid];
}

extern "C" void kernel_launch(void* const* d_in, const int* in_sizes, int n_in,
                              void* d_out, int out_size) {
    const float* x   = (const float*)d_in[0];
    const float* emb = (const float*)d_in[1];
    float* out       = (float*)d_out;

    vq_prep_kernel<<<64, 128>>>(emb);
    vq_mma_kernel<<<L_TOTAL / MT, THREADS>>>(x, emb, out);
}

// round 13
// speedup vs baseline: 1.0678x; 1.0678x over previous
#include <cuda_runtime.h>
#include <cuda_fp16.h>

#define L_TOTAL 32768
#define KQ      1024
#define EDIM    64
#define MT      32             // latents per CTA (2 tiles x 16)
#define KHALF   512            // codes per k-split half
#define CHK     16             // codes per staged chunk per half
#define NCHUNK  (KHALF / CHK)  // 32
#define SROW    72             // padded smem row stride (halves) -> conflict-free
#define THREADS 128

// scratch tables (no cudaMalloc allowed)
__device__ float  g_c[KQ];             // ||e_k||^2 (fp32)
__device__ __half g_ehi[KQ * EDIM];    // fp16-rounded embeddings [k][e]
__device__ __half g_elo[KQ * EDIM];    // residual

__device__ __forceinline__ void mma16816(float* d, const unsigned* a,
                                         unsigned b0, unsigned b1) {
    asm volatile(
        "mma.sync.aligned.m16n8k16.row.col.f32.f16.f16.f32 "
        "{%0,%1,%2,%3}, {%4,%5,%6,%7}, {%8,%9}, {%0,%1,%2,%3};"
        : "+f"(d[0]), "+f"(d[1]), "+f"(d[2]), "+f"(d[3])
        : "r"(a[0]), "r"(a[1]), "r"(a[2]), "r"(a[3]), "r"(b0), "r"(b1));
}

__device__ __forceinline__ void ldsm4(unsigned& r0, unsigned& r1,
                                      unsigned& r2, unsigned& r3,
                                      unsigned addr) {
    asm volatile("ldmatrix.sync.aligned.m8n8.x4.shared.b16 {%0,%1,%2,%3}, [%4];"
                 : "=r"(r0), "=r"(r1), "=r"(r2), "=r"(r3) : "r"(addr));
}

__device__ __forceinline__ unsigned packsplit(float a, float b, unsigned& lo) {
    __half ha = __float2half_rn(a), hb = __float2half_rn(b);
    float la = a - __half2float(ha), lb = b - __half2float(hb);
    __half2 H = __halves2half2(ha, hb);
    __half2 L = __halves2half2(__float2half_rn(la), __float2half_rn(lb));
    lo = *reinterpret_cast<unsigned*>(&L);
    return *reinterpret_cast<unsigned*>(&H);
}

__device__ __forceinline__ unsigned packhi(float a, float b) {
    __half2 H = __halves2half2(__float2half_rn(a), __float2half_rn(b));
    return *reinterpret_cast<unsigned*>(&H);
}

__device__ __forceinline__ void cp16(void* dst_smem, const void* src) {
    unsigned d = (unsigned)__cvta_generic_to_shared(dst_smem);
    asm volatile("cp.async.cg.shared.global [%0], [%1], 16;"
                 :: "r"(d), "l"(src) : "memory");
}

// Parallel prep: 8 threads per code row. ||e||^2 via 8-lane shfl tree.
__global__ void vq_prep_kernel(const float* __restrict__ emb) {
    int t   = blockIdx.x * blockDim.x + threadIdx.x;  // 0..8191
    int k   = t >> 3;
    int seg = t & 7;
    const float4* p = reinterpret_cast<const float4*>(emb + k * EDIM + seg * 8);
    float4 v0 = p[0], v1 = p[1];
    float s = v0.x * v0.x + v0.y * v0.y + v0.z * v0.z + v0.w * v0.w
            + v1.x * v1.x + v1.y * v1.y + v1.z * v1.z + v1.w * v1.w;
    uint4 H, L;
    H.x = packsplit(v0.x, v0.y, L.x);
    H.y = packsplit(v0.z, v0.w, L.y);
    H.z = packsplit(v1.x, v1.y, L.z);
    H.w = packsplit(v1.z, v1.w, L.w);
    *reinterpret_cast<uint4*>(&g_ehi[k * EDIM + seg * 8]) = H;
    *reinterpret_cast<uint4*>(&g_elo[k * EDIM + seg * 8]) = L;
    s += __shfl_xor_sync(0xffffffffu, s, 1);
    s += __shfl_xor_sync(0xffffffffu, s, 2);
    s += __shfl_xor_sync(0xffffffffu, s, 4);
    if (seg == 0) g_c[k] = s;
}

struct Top2 { float b1, b2; int i1, i2; };

__device__ __forceinline__ void upd(Top2& t, float s, int c) {
    if (s < t.b1)      { t.b2 = t.b1; t.i2 = t.i1; t.b1 = s; t.i1 = c; }
    else if (s < t.b2) { t.b2 = s; t.i2 = c; }
}

__global__ void __launch_bounds__(THREADS, 7)
vq_mma_kernel(const float* __restrict__ x,
              const float* __restrict__ emb,
              float* __restrict__ out) {
    // [buf][half][tab(hi/lo)] double-buffered code chunks
    __shared__ __align__(16) __half sB[2][2][2][CHK * SROW];
    __shared__ float cs[KQ];
    __shared__ float mb1[MT], mb2[MT];
    __shared__ int   mi1[MT], mi2[MT];
    __shared__ int   sidx[MT];

    const int tid   = threadIdx.x;
    const int warp  = tid >> 5;
    const int lane  = tid & 31;
    const int g     = lane >> 2;       // row within m16 tile
    const int T     = lane & 3;        // thread in quad
    const int tile  = warp & 1;        // which 16-latent tile
    const int khalf = warp >> 1;       // which 512-code half
    const int lbase = blockIdx.x * MT;

    // stage ||e||^2
    #pragma unroll
    for (int i = 0; i < KQ / THREADS; i++)
        cs[tid + i * THREADS] = g_c[tid + i * THREADS];

    // Block-wide staging (proven R11 form): 512 16B moves -> 4 per thread.
    auto stage = [&](int ch, int buf) {
        #pragma unroll
        for (int i = 0; i < 4; i++) {
            int u    = tid + i * THREADS;      // 0..511
            int seg  = u & 7;
            int row  = (u >> 3) & 15;
            int tab  = (u >> 7) & 1;
            int half = u >> 8;
            const __half* src = tab ? g_elo : g_ehi;
            cp16(&sB[buf][half][tab][row * SROW + seg * 8],
                 &src[(size_t)(half * KHALF + ch * CHK + row) * EDIM + seg * 8]);
        }
        asm volatile("cp.async.commit_group;" ::: "memory");
    };

    stage(0, 0);

    // ldmatrix per-lane base offsets (verified mapping, rel_err 0.0):
    const unsigned lane_off =
        (unsigned)(((lane & 7) + ((lane >> 4) << 3)) * (SROW * 2)
                   + ((lane >> 3) & 1) * 16);
    const unsigned sm_hi0 =
        (unsigned)__cvta_generic_to_shared(&sB[0][khalf][0][0]) + lane_off;
    const unsigned sm_lo0 =
        (unsigned)__cvta_generic_to_shared(&sB[0][khalf][1][0]) + lane_off;
    const unsigned BUFSTRIDE = 2u * 2u * CHK * SROW * 2u;   // bytes per buf

    // A fragments: rows r0 = tile*16+g, r1 = r0+8 of (-2x), fp16-hi only.
    unsigned ahi[4][4];
    {
        const float* xr0 = x + (size_t)(lbase + tile * 16 + g) * EDIM;
        const float* xr1 = xr0 + 8 * EDIM;
        #pragma unroll
        for (int ks = 0; ks < 4; ks++) {
            int c0 = 16 * ks + 2 * T;
            float2 v;
            v = *reinterpret_cast<const float2*>(xr0 + c0);
            ahi[ks][0] = packhi(-2.f * v.x, -2.f * v.y);
            v = *reinterpret_cast<const float2*>(xr1 + c0);
            ahi[ks][1] = packhi(-2.f * v.x, -2.f * v.y);
            v = *reinterpret_cast<const float2*>(xr0 + c0 + 8);
            ahi[ks][2] = packhi(-2.f * v.x, -2.f * v.y);
            v = *reinterpret_cast<const float2*>(xr1 + c0 + 8);
            ahi[ks][3] = packhi(-2.f * v.x, -2.f * v.y);
        }
    }

    Top2 tp[2];
    tp[0].b1 = tp[0].b2 = 3.4e38f; tp[0].i1 = tp[0].i2 = 0;
    tp[1].b1 = tp[1].b2 = 3.4e38f; tp[1].i1 = tp[1].i2 = 0;

    // Score chunk cc's accumulators (deferred by one chunk in the pipeline).
    float d[2][4];
    auto score = [&](int cc) {
        const int c0 = khalf * KHALF + cc * CHK;
        #pragma unroll
        for (int j = 0; j < 2; j++) {
            int col = c0 + 8 * j + 2 * T;
            upd(tp[0], cs[col]     + d[j][0], col);
            upd(tp[0], cs[col + 1] + d[j][1], col + 1);
            upd(tp[1], cs[col]     + d[j][2], col);
            upd(tp[1], cs[col + 1] + d[j][3], col + 1);
        }
    };

    asm volatile("cp.async.wait_group 0;" ::: "memory");
    __syncthreads();   // covers cs staging + chunk 0

    // ---- pipeline prologue: compute chunk 0 into d (no scoring yet) ----
    {
        const unsigned base_hi = sm_hi0;
        const unsigned base_lo = sm_lo0;
        #pragma unroll
        for (int j = 0; j < 2; j++)
            #pragma unroll
            for (int r = 0; r < 4; r++) d[j][r] = 0.f;
        unsigned h0[4], h1[4], l0[4], l1[4];
        ldsm4(h0[0], h0[1], h0[2], h0[3], base_hi);
        ldsm4(h1[0], h1[1], h1[2], h1[3], base_hi + 32);
        ldsm4(l0[0], l0[1], l0[2], l0[3], base_lo);
        ldsm4(l1[0], l1[1], l1[2], l1[3], base_lo + 32);
        stage(1, 1);   // prefetch chunk 1 while chunk-0 MMAs run
        #pragma unroll
        for (int j = 0; j < 2; j++) {
            mma16816(d[j], ahi[0], h0[2*j], h0[2*j+1]);
            mma16816(d[j], ahi[0], l0[2*j], l0[2*j+1]);
            mma16816(d[j], ahi[1], h1[2*j], h1[2*j+1]);
            mma16816(d[j], ahi[1], l1[2*j], l1[2*j+1]);
        }
        ldsm4(h0[0], h0[1], h0[2], h0[3], base_hi + 64);
        ldsm4(h1[0], h1[1], h1[2], h1[3], base_hi + 96);
        ldsm4(l0[0], l0[1], l0[2], l0[3], base_lo + 64);
        ldsm4(l1[0], l1[1], l1[2], l1[3], base_lo + 96);
        #pragma unroll
        for (int j = 0; j < 2; j++) {
            mma16816(d[j], ahi[2], h0[2*j], h0[2*j+1]);
            mma16816(d[j], ahi[2], l0[2*j], l0[2*j+1]);
            mma16816(d[j], ahi[3], h1[2*j], h1[2*j+1]);
            mma16816(d[j], ahi[3], l1[2*j], l1[2*j+1]);
        }
    }

    // ---- main pipelined loop: score(ch-1) hides LDSM(ch) latency ----
    #pragma unroll 1
    for (int ch = 1; ch < NCHUNK; ch++) {
        asm volatile("cp.async.wait_group 0;" ::: "memory");
        __syncthreads();                       // chunk ch staged; buf ch-1 free

        const int buf = ch & 1;
        const unsigned base_hi = sm_hi0 + (unsigned)buf * BUFSTRIDE;
        const unsigned base_lo = sm_lo0 + (unsigned)buf * BUFSTRIDE;

        unsigned h0[4], h1[4], l0[4], l1[4];
        ldsm4(h0[0], h0[1], h0[2], h0[3], base_hi);
        ldsm4(h1[0], h1[1], h1[2], h1[3], base_hi + 32);
        ldsm4(l0[0], l0[1], l0[2], l0[3], base_lo);
        ldsm4(l1[0], l1[1], l1[2], l1[3], base_lo + 32);

        if (ch + 1 < NCHUNK) stage(ch + 1, buf ^ 1);

        score(ch - 1);                         // consume previous d (ALU,
                                               // overlaps LDSM/MMA latency)
        #pragma unroll
        for (int j = 0; j < 2; j++)
            #pragma unroll
            for (int r = 0; r < 4; r++) d[j][r] = 0.f;
        #pragma unroll
        for (int j = 0; j < 2; j++) {
            mma16816(d[j], ahi[0], h0[2*j], h0[2*j+1]);
            mma16816(d[j], ahi[0], l0[2*j], l0[2*j+1]);
            mma16816(d[j], ahi[1], h1[2*j], h1[2*j+1]);
            mma16816(d[j], ahi[1], l1[2*j], l1[2*j+1]);
        }
        ldsm4(h0[0], h0[1], h0[2], h0[3], base_hi + 64);
        ldsm4(h1[0], h1[1], h1[2], h1[3], base_hi + 96);
        ldsm4(l0[0], l0[1], l0[2], l0[3], base_lo + 64);
        ldsm4(l1[0], l1[1], l1[2], l1[3], base_lo + 96);
        #pragma unroll
        for (int j = 0; j < 2; j++) {
            mma16816(d[j], ahi[2], h0[2*j], h0[2*j+1]);
            mma16816(d[j], ahi[2], l0[2*j], l0[2*j+1]);
            mma16816(d[j], ahi[3], h1[2*j], h1[2*j+1]);
            mma16816(d[j], ahi[3], l1[2*j], l1[2*j+1]);
        }
    }
    score(NCHUNK - 1);                         // pipeline epilogue

    // Reduce across the 4 lanes of each quad (xor 1, 2 stay in-quad).
    #pragma unroll
    for (int s = 0; s < 2; s++) {
        #pragma unroll
        for (int m = 1; m < 4; m <<= 1) {
            float ob1 = __shfl_xor_sync(0xffffffffu, tp[s].b1, m);
            float ob2 = __shfl_xor_sync(0xffffffffu, tp[s].b2, m);
            int   oi1 = __shfl_xor_sync(0xffffffffu, tp[s].i1, m);
            int   oi2 = __shfl_xor_sync(0xffffffffu, tp[s].i2, m);
            bool of = (ob1 < tp[s].b1) || (ob1 == tp[s].b1 && oi1 < tp[s].i1);
            if (of) {
                bool t2 = (tp[s].b1 < ob2) || (tp[s].b1 == ob2 && tp[s].i1 < oi2);
                tp[s].b2 = t2 ? tp[s].b1 : ob2;
                tp[s].i2 = t2 ? tp[s].i1 : oi2;
                tp[s].b1 = ob1; tp[s].i1 = oi1;
            } else {
                bool t2 = (ob1 < tp[s].b2) || (ob1 == tp[s].b2 && oi1 < tp[s].i2);
                if (t2) { tp[s].b2 = ob1; tp[s].i2 = oi1; }
            }
        }
    }

    // k-half merge: khalf1 publishes, khalf0 merges (half0 idx < half1 idx,
    // strict < keeps first-min semantics).
    if (khalf == 1 && T == 0) {
        #pragma unroll
        for (int s = 0; s < 2; s++) {
            int lr = tile * 16 + g + 8 * s;
            mb1[lr] = tp[s].b1; mi1[lr] = tp[s].i1;
            mb2[lr] = tp[s].b2; mi2[lr] = tp[s].i2;
        }
    }
    __syncthreads();

    if (khalf == 0 && T == 0) {
        #pragma unroll
        for (int s = 0; s < 2; s++) {
            int lr = tile * 16 + g + 8 * s;
            float ob1 = mb1[lr], ob2 = mb2[lr];
            int   oi1 = mi1[lr], oi2 = mi2[lr];
            if (ob1 < tp[s].b1) {
                bool t2 = (tp[s].b1 <= ob2);
                tp[s].b2 = t2 ? tp[s].b1 : ob2;
                tp[s].i2 = t2 ? tp[s].i1 : oi2;
                tp[s].b1 = ob1; tp[s].i1 = oi1;
            } else if (ob1 < tp[s].b2) {
                tp[s].b2 = ob1; tp[s].i2 = oi1;
            }

            int win = tp[s].i1;
            // Widened guard (2-pass split): exact fp32 recheck when close.
            if (tp[s].b2 - tp[s].b1 < 3e-2f) {
                const float* xr  = x   + (size_t)(lbase + lr) * EDIM;
                const float* e1r = emb + (size_t)tp[s].i1 * EDIM;
                const float* e2r = emb + (size_t)tp[s].i2 * EDIM;
                float d1 = 0.f, d2 = 0.f;
                #pragma unroll 8
                for (int e = 0; e < EDIM; e++) {
                    float xv = xr[e];
                    d1 = fmaf(xv, e1r[e], d1);
                    d2 = fmaf(xv, e2r[e], d2);
                }
                float s1 = fmaf(-2.f, d1, cs[tp[s].i1]);
                float s2 = fmaf(-2.f, d2, cs[tp[s].i2]);
                if (s2 < s1 || (s2 == s1 && tp[s].i2 < tp[s].i1)) win = tp[s].i2;
            }
            sidx[lr] = win;
        }
    }
    __syncthreads();

    // Coalesced epilogue: out = [x | quantized | z_hat | indices], fp32.
    const size_t LE4 = (size_t)L_TOTAL * (EDIM / 4);
    const float4* x4  = reinterpret_cast<const float4*>(x);
    const float4* e4p = reinterpret_cast<const float4*>(emb);
    float4* out4 = reinterpret_cast<float4*>(out);
    #pragma unroll
    for (int i = 0; i < (MT * EDIM / 4) / THREADS; i++) {
        int idx = tid + i * THREADS;
        int l = idx >> 4, c4 = idx & 15;
        size_t goff = (size_t)(lbase + l) * 16 + c4;
        float4 xv = x4[goff];
        float4 qv = e4p[(size_t)sidx[l] * 16 + c4];
        out4[goff] = xv;
        out4[LE4 + goff] = qv;
        float4 zh;
        zh.x = (xv.x + qv.x) - xv.x;
        zh.y = (xv.y + qv.y) - xv.y;
        zh.z = (xv.z + qv.z) - xv.z;
        zh.w = (xv.w + qv.w) - xv.w;
        out4[2 * LE4 + goff] = zh;
    }
    if (tid < MT)
        out[3 * (size_t)L_TOTAL * EDIM + lbase + tid] = (float)sidx[tid];
}

extern "C" void kernel_launch(void* const* d_in, const int* in_sizes, int n_in,
                              void* d_out, int out_size) {
    const float* x   = (const float*)d_in[0];
    const float* emb = (const float*)d_in[1];
    float* out       = (float*)d_out;

    vq_prep_kernel<<<64, 128>>>(emb);
    vq_mma_kernel<<<L_TOTAL / MT, THREADS>>>(x, emb, out);
}